// round 16
// baseline (speedup 1.0000x reference)
#include <cuda_runtime.h>
#include <cuda_bf16.h>
#include <math.h>
#include <stdint.h>

// Problem dims (fixed)
#define BDIM 128
#define TDIM 512
#define IDIM 512
#define HDIM 1024
#define G4   4096
#define ODIM 512
#define MROWS (BDIM * TDIM)  // 65536

typedef unsigned long long ull;

// Packed dual-fp32 FMA (B300 FFMA2) — exact fp32, 2x throughput, only via PTX.
__device__ __forceinline__ void ffma2(ull& d, ull a, ull b) {
    asm("fma.rn.f32x2 %0, %1, %2, %0;" : "+l"(d) : "l"(a), "l"(b));
}
__device__ __forceinline__ float lo32(ull u) { return __uint_as_float((unsigned)u); }
__device__ __forceinline__ float hi32(ull u) { return __uint_as_float((unsigned)(u >> 32)); }

// ---------------- Scratch (static device allocations; no cudaMalloc) ----------
__device__ float g_xg[(size_t)TDIM * BDIM * G4];     // [T,B,4H] 1 GiB
__device__ float g_hout[(size_t)BDIM * TDIM * HDIM]; // [B,T,H] 256 MiB
__device__ float g_hA[BDIM * HDIM];                  // recurrent h double buffer
__device__ float g_hB[BDIM * HDIM];
// bf16 split-precision operands for tensor-core GEMMs
__device__ __nv_bfloat16 g_Ahi[(size_t)MROWS * HDIM];  // 128 MiB
__device__ __nv_bfloat16 g_Alo[(size_t)MROWS * HDIM];  // 128 MiB
__device__ __nv_bfloat16 g_Whi[(size_t)G4 * HDIM];     // 8 MiB
__device__ __nv_bfloat16 g_Wlo[(size_t)G4 * HDIM];     // 8 MiB

// ---------------- Split grid barrier (arrive / wait) -----------------------
__device__ unsigned g_cnt = 0;
__device__ volatile unsigned g_gen = 0;

__device__ __forceinline__ void gb_arrive(unsigned nb) {
    __threadfence();
    __syncthreads();
    if (threadIdx.x == 0) {
        unsigned old = atomicAdd(&g_cnt, 1u);
        if (old == nb - 1u) {
            g_cnt = 0;
            __threadfence();
            g_gen = g_gen + 1u;
        }
    }
}
__device__ __forceinline__ void gb_wait(unsigned target) {
    if (threadIdx.x == 0) {
        while ((int)(g_gen - target) < 0) { }
    }
    __syncthreads();
}

__device__ __forceinline__ float sigmoidf_(float x) {
    return 1.0f / (1.0f + __expf(-x));
}

// ===================== baseline-PTX tensor-core helpers ====================
__device__ __forceinline__ uint32_t smem_u32(const void* p) {
    uint32_t a;
    asm("{ .reg .u64 t; cvta.to.shared.u64 t, %1; cvt.u32.u64 %0, t; }" : "=r"(a) : "l"(p));
    return a;
}
#define SWZ(o) ((o) ^ ((((unsigned)(o)) >> 3) & 0x70u))

__device__ __forceinline__ void ldsm_x4(uint32_t r[4], uint32_t addr) {
    asm volatile("ldmatrix.sync.aligned.m8n8.x4.shared.b16 {%0,%1,%2,%3}, [%4];"
                 : "=r"(r[0]), "=r"(r[1]), "=r"(r[2]), "=r"(r[3]) : "r"(addr));
}
__device__ __forceinline__ void mma_bf16(float c[4], const uint32_t a[4], const uint32_t b[2]) {
    asm volatile(
        "mma.sync.aligned.m16n8k16.row.col.f32.bf16.bf16.f32 "
        "{%0,%1,%2,%3}, {%4,%5,%6,%7}, {%8,%9}, {%0,%1,%2,%3};"
        : "+f"(c[0]), "+f"(c[1]), "+f"(c[2]), "+f"(c[3])
        : "r"(a[0]), "r"(a[1]), "r"(a[2]), "r"(a[3]), "r"(b[0]), "r"(b[1]));
}
__device__ __forceinline__ void cp16(uint32_t saddr, const void* g) {
    asm volatile("cp.async.cg.shared.global [%0], [%1], 16;" :: "r"(saddr), "l"(g));
}
#define CP_COMMIT() asm volatile("cp.async.commit_group;" ::: "memory")
#define CP_WAIT(n)  asm volatile("cp.async.wait_group %0;" :: "n"(n) : "memory")

// ---------------- bf16 split kernel ----------------------------------------
__global__ void split_bf16(const float* __restrict__ in,
                           __nv_bfloat16* __restrict__ hi,
                           __nv_bfloat16* __restrict__ lo, size_t n2) {
    size_t i = (size_t)blockIdx.x * blockDim.x + threadIdx.x;
    size_t stride = (size_t)gridDim.x * blockDim.x;
    const float2* in2 = (const float2*)in;
    __nv_bfloat162* h2 = (__nv_bfloat162*)hi;
    __nv_bfloat162* l2 = (__nv_bfloat162*)lo;
    for (; i < n2; i += stride) {
        float2 v = in2[i];
        __nv_bfloat16 hx = __float2bfloat16_rn(v.x);
        __nv_bfloat16 hy = __float2bfloat16_rn(v.y);
        float lx = v.x - __bfloat162float(hx);
        float ly = v.y - __bfloat162float(hy);
        __nv_bfloat162 hh; hh.x = hx; hh.y = hy;
        __nv_bfloat162 ll; ll.x = __float2bfloat16_rn(lx); ll.y = __float2bfloat16_rn(ly);
        h2[i] = hh;
        l2[i] = ll;
    }
}

// ---------------- HMMA split-precision GEMM (unchanged) --------------------
#define GM_TILE_B   16384                 // 128 rows x 128 bytes
#define GM_STAGE_B  (4 * GM_TILE_B)       // 64 KiB
#define GM_SMEM     (1024 + 2 * GM_STAGE_B)

__global__ __launch_bounds__(256, 1) void gemm_mma(
    const __nv_bfloat16* __restrict__ Ahi, const __nv_bfloat16* __restrict__ Alo,
    const __nv_bfloat16* __restrict__ Bhi, const __nv_bfloat16* __restrict__ Blo,
    const float* __restrict__ b1, const float* __restrict__ b2,
    float* __restrict__ C, int K, int N, int swap)
{
    extern __shared__ char dsm[];
    const int tid = threadIdx.x;
    const int lane = tid & 31;
    const int warp = tid >> 5;
    const int m0 = blockIdx.y << 7;
    const int n0 = blockIdx.x << 7;
    const int wm = (warp >> 1) << 5;   // 0,32,64,96
    const int wn = (warp & 1) << 6;    // 0,64

    uint32_t sb = (smem_u32(dsm) + 1023u) & ~1023u;

    const int lrow = tid & 127;
    const int lcp  = (tid >> 7) << 2;  // chunk base 0 or 4 (x16B)

    auto load_tile = [&](uint32_t sdst, const __nv_bfloat16* gsrc, int row0, int kc) {
        const __nv_bfloat16* g = gsrc + (size_t)(row0 + lrow) * K + kc * 64 + lcp * 8;
        uint32_t ob = (uint32_t)lrow * 128u + (uint32_t)lcp * 16u;
#pragma unroll
        for (int j = 0; j < 4; j++)
            cp16(sdst + SWZ(ob + j * 16u), g + j * 8);
    };
    auto load_stage = [&](uint32_t stage, int kc) {
        uint32_t base = sb + stage * GM_STAGE_B;
        load_tile(base,                Ahi, m0, kc);
        load_tile(base + GM_TILE_B,    Alo, m0, kc);
        load_tile(base + 2 * GM_TILE_B, Bhi, n0, kc);
        load_tile(base + 3 * GM_TILE_B, Blo, n0, kc);
        CP_COMMIT();
    };

    float acc[2][8][4];
#pragma unroll
    for (int mf = 0; mf < 2; mf++)
#pragma unroll
        for (int f = 0; f < 8; f++)
#pragma unroll
            for (int e = 0; e < 4; e++) acc[mf][f][e] = 0.0f;

    const uint32_t a_off = (uint32_t)(wm + (lane & 15)) * 128u + (uint32_t)(lane >> 4) * 16u;
    const uint32_t b_row = (uint32_t)(wn + ((lane >> 4) << 3) + (lane & 7));
    const uint32_t b_off = b_row * 128u + (uint32_t)((lane >> 3) & 1) * 16u;

    const int nc = K >> 6;
    load_stage(0, 0);

#pragma unroll 1
    for (int c = 0; c < nc; ++c) {
        if (c + 1 < nc) load_stage((c + 1) & 1, c + 1);
        if (c + 1 < nc) { CP_WAIT(1); } else { CP_WAIT(0); }
        __syncthreads();

        uint32_t base = sb + (uint32_t)(c & 1) * GM_STAGE_B;
        uint32_t pAh = base;
        uint32_t pAl = base + GM_TILE_B;
        uint32_t pBh = base + 2 * GM_TILE_B;
        uint32_t pBl = base + 3 * GM_TILE_B;

#pragma unroll
        for (int ks = 0; ks < 4; ks++) {
            uint32_t ko = (uint32_t)ks * 32u;
            uint32_t ahi[2][4], alo[2][4];
#pragma unroll
            for (int mf = 0; mf < 2; mf++) {
                uint32_t off = a_off + (uint32_t)(mf << 11) + ko;
                ldsm_x4(ahi[mf], pAh + SWZ(off));
                ldsm_x4(alo[mf], pAl + SWZ(off));
            }
            uint32_t bhi[8][2], blo[8][2];
#pragma unroll
            for (int nq = 0; nq < 4; nq++) {
                uint32_t off = b_off + (uint32_t)(nq << 11) + ko;
                uint32_t r[4];
                ldsm_x4(r, pBh + SWZ(off));
                bhi[2 * nq][0] = r[0]; bhi[2 * nq][1] = r[1];
                bhi[2 * nq + 1][0] = r[2]; bhi[2 * nq + 1][1] = r[3];
                ldsm_x4(r, pBl + SWZ(off));
                blo[2 * nq][0] = r[0]; blo[2 * nq][1] = r[1];
                blo[2 * nq + 1][0] = r[2]; blo[2 * nq + 1][1] = r[3];
            }
#pragma unroll
            for (int mf = 0; mf < 2; mf++)
#pragma unroll
                for (int f = 0; f < 8; f++) {
                    mma_bf16(acc[mf][f], ahi[mf], bhi[f]);
                    mma_bf16(acc[mf][f], ahi[mf], blo[f]);
                    mma_bf16(acc[mf][f], alo[mf], bhi[f]);
                }
        }
        __syncthreads();
    }

#pragma unroll
    for (int mf = 0; mf < 2; mf++) {
        int mA = m0 + wm + mf * 16 + (lane >> 2);
        int mB = mA + 8;
        int rA = swap ? ((mA & (TDIM - 1)) * BDIM + (mA >> 9)) : mA;
        int rB = swap ? ((mB & (TDIM - 1)) * BDIM + (mB >> 9)) : mB;
        float* CA = C + (size_t)rA * N;
        float* CB = C + (size_t)rB * N;
#pragma unroll
        for (int f = 0; f < 8; f++) {
            int n = n0 + wn + f * 8 + ((lane & 3) << 1);
            float bb0 = b1[n] + (b2 ? b2[n] : 0.0f);
            float bb1 = b1[n + 1] + (b2 ? b2[n + 1] : 0.0f);
            float2 v0 = make_float2(acc[mf][f][0] + bb0, acc[mf][f][1] + bb1);
            float2 v1 = make_float2(acc[mf][f][2] + bb0, acc[mf][f][3] + bb1);
            *(float2*)(CA + n) = v0;
            *(float2*)(CB + n) = v1;
        }
    }
}

// ---------------- Persistent LSTM scan (FFMA2, k-pair packing) -------------
// 128 CTAs (4 b-tiles x 32 h-tiles) x 256 threads (2 warps/SMSP).
// FFMA2 lanes = independent even/odd-k partial sums: operands are natural
// contiguous (a_{2k},a_{2k+1}) / (w_{2k},w_{2k+1}) pairs — no duplication.
// smem layout [kpair][row] so A fragments stay contiguous. Warp tile
// 8b x 64col; lane = 2 cols. Final acc = lo+hi (exact fp32, reassociated).
__global__ __launch_bounds__(256, 1) void lstm_scan(const float* __restrict__ Whh)
{
    __shared__ alignas(16) float As2[2][8][68];    // [buf][kk][2*row], pad 68
    __shared__ alignas(16) float Bs2[2][8][260];   // [buf][kk][2*col], pad 260
    __shared__ alignas(16) float gsm[32][128];     // gates staging
    __shared__ float csm[32][32];                  // cell state (persistent)

    const int tid = threadIdx.x;
    const int b0 = (blockIdx.x >> 5) << 5;
    const int h0 = (blockIdx.x & 31) << 5;
    const unsigned nb = gridDim.x;

    const unsigned gbase = g_gen;   // read before any arrive

    // zero c and the initial h buffer (this CTA's (b,h) block)
    for (int q = tid; q < 1024; q += 256) {
        csm[q >> 5][q & 31] = 0.0f;
        g_hA[(b0 + (q >> 5)) * HDIM + h0 + (q & 31)] = 0.0f;
    }
    gb_arrive(nb);

    // compute mapping: warp -> 8 b-rows x 64 cols; lane -> 2 cols
    const int bg = (tid >> 6);        // warp>>1: 0..3 -> rows 8bg..8bg+7
    const int ch = (tid >> 5) & 1;    // col half 0/1
    const int l  = tid & 31;
    const int r0 = bg << 3;
    const int cc = (ch << 6) + (l << 1);   // lane's first col (of 2)

    // A loader (threads 0..127): row ar, k-quad aq in {0,4,8,12}
    const int ar = tid >> 2;          // 0..31 (valid when tid<128)
    const int aq = (tid & 3) << 2;
    const int akk = aq >> 1;          // kk base for this quad

    // B loader (all 256): col cb, quads {2qh, 2qh+1}
    const int cb = tid & 127;
    const int qh = tid >> 7;          // 0/1
    const int bkk = qh << 2;          // kk base
    const int wrow = ((cb >> 5) << 10) + h0 + (cb & 31);  // gate*1024 + h
    const float* Wp = Whh + (size_t)wrow * HDIM + (qh << 3);

    // elementwise mapping: 4 cells per thread
    const int eb = tid >> 3;           // 0..31
    const int eh = (tid & 7) << 2;     // 0..28

#pragma unroll 1
    for (int t = 0; t < TDIM; ++t) {
        const float* hp = (t & 1) ? g_hB : g_hA;
        float* hn = (t & 1) ? g_hA : g_hB;
        const float* Ap = hp + (b0 + ar) * HDIM + aq;

        // ---- h-independent work BEFORE the barrier wait ----
        const size_t xb = ((size_t)t * BDIM + b0 + eb) * G4 + h0 + eh;
        float4 xi = __ldcs((const float4*)&g_xg[xb]);
        float4 xf = __ldcs((const float4*)&g_xg[xb + 1024]);
        float4 xgv = __ldcs((const float4*)&g_xg[xb + 2048]);
        float4 xo = __ldcs((const float4*)&g_xg[xb + 3072]);

        // W tile-0 stage (safe: prior step's epilogue sync passed)
        {
            float4 w0 = *(const float4*)Wp;
            float4 w1 = *(const float4*)(Wp + 4);
            *(float2*)&Bs2[0][bkk + 0][2 * cb] = make_float2(w0.x, w0.y);
            *(float2*)&Bs2[0][bkk + 1][2 * cb] = make_float2(w0.z, w0.w);
            *(float2*)&Bs2[0][bkk + 2][2 * cb] = make_float2(w1.x, w1.y);
            *(float2*)&Bs2[0][bkk + 3][2 * cb] = make_float2(w1.z, w1.w);
        }

        // ---- wait for h(t-1) from all CTAs ----
        gb_wait(gbase + t + 1);

        // A tile-0 stage
        if (tid < 128) {
            float4 ra = __ldcg((const float4*)Ap);
            *(float2*)&As2[0][akk + 0][2 * ar] = make_float2(ra.x, ra.y);
            *(float2*)&As2[0][akk + 1][2 * ar] = make_float2(ra.z, ra.w);
        }
        __syncthreads();

        ull acc[16];
#pragma unroll
        for (int i = 0; i < 16; i++) acc[i] = 0ULL;

        // initial fragments (kk = 0 of tile 0)
        ulonglong2 fa0 = *(const ulonglong2*)&As2[0][0][2 * r0];
        ulonglong2 fa1 = *(const ulonglong2*)&As2[0][0][2 * r0 + 4];
        ulonglong2 fa2 = *(const ulonglong2*)&As2[0][0][2 * r0 + 8];
        ulonglong2 fa3 = *(const ulonglong2*)&As2[0][0][2 * r0 + 12];
        ulonglong2 fb = *(const ulonglong2*)&Bs2[0][0][2 * cc];

        float4 ra2 = make_float4(0.f, 0.f, 0.f, 0.f), rw0, rw1;
        int cur = 0;
#pragma unroll 1
        for (int kt = 0; kt < 64; ++kt) {
            if (kt < 63) {
                int ko = (kt + 1) << 4;
                if (tid < 128) ra2 = __ldcg((const float4*)(Ap + ko));
                rw0 = *(const float4*)(Wp + ko);
                rw1 = *(const float4*)(Wp + ko + 4);
            }
#pragma unroll
            for (int kk = 0; kk < 8; ++kk) {
                ulonglong2 na0, na1, na2, na3, nb2;
                if (kk < 7) {
                    na0 = *(const ulonglong2*)&As2[cur][kk + 1][2 * r0];
                    na1 = *(const ulonglong2*)&As2[cur][kk + 1][2 * r0 + 4];
                    na2 = *(const ulonglong2*)&As2[cur][kk + 1][2 * r0 + 8];
                    na3 = *(const ulonglong2*)&As2[cur][kk + 1][2 * r0 + 12];
                    nb2 = *(const ulonglong2*)&Bs2[cur][kk + 1][2 * cc];
                }
                ffma2(acc[0],  fa0.x, fb.x); ffma2(acc[1],  fa0.x, fb.y);
                ffma2(acc[2],  fa0.y, fb.x); ffma2(acc[3],  fa0.y, fb.y);
                ffma2(acc[4],  fa1.x, fb.x); ffma2(acc[5],  fa1.x, fb.y);
                ffma2(acc[6],  fa1.y, fb.x); ffma2(acc[7],  fa1.y, fb.y);
                ffma2(acc[8],  fa2.x, fb.x); ffma2(acc[9],  fa2.x, fb.y);
                ffma2(acc[10], fa2.y, fb.x); ffma2(acc[11], fa2.y, fb.y);
                ffma2(acc[12], fa3.x, fb.x); ffma2(acc[13], fa3.x, fb.y);
                ffma2(acc[14], fa3.y, fb.x); ffma2(acc[15], fa3.y, fb.y);
                if (kk < 7) { fa0 = na0; fa1 = na1; fa2 = na2; fa3 = na3; fb = nb2; }
            }
            if (kt < 63) {
                cur ^= 1;
                if (tid < 128) {
                    *(float2*)&As2[cur][akk + 0][2 * ar] = make_float2(ra2.x, ra2.y);
                    *(float2*)&As2[cur][akk + 1][2 * ar] = make_float2(ra2.z, ra2.w);
                }
                *(float2*)&Bs2[cur][bkk + 0][2 * cb] = make_float2(rw0.x, rw0.y);
                *(float2*)&Bs2[cur][bkk + 1][2 * cb] = make_float2(rw0.z, rw0.w);
                *(float2*)&Bs2[cur][bkk + 2][2 * cb] = make_float2(rw1.x, rw1.y);
                *(float2*)&Bs2[cur][bkk + 3][2 * cb] = make_float2(rw1.z, rw1.w);
                __syncthreads();
                fa0 = *(const ulonglong2*)&As2[cur][0][2 * r0];
                fa1 = *(const ulonglong2*)&As2[cur][0][2 * r0 + 4];
                fa2 = *(const ulonglong2*)&As2[cur][0][2 * r0 + 8];
                fa3 = *(const ulonglong2*)&As2[cur][0][2 * r0 + 12];
                fb = *(const ulonglong2*)&Bs2[cur][0][2 * cc];
            }
        }

        // reduce even/odd partials and stage gates
#pragma unroll
        for (int r = 0; r < 8; r++) {
            float f0 = lo32(acc[2 * r]) + hi32(acc[2 * r]);
            float f1 = lo32(acc[2 * r + 1]) + hi32(acc[2 * r + 1]);
            *(float2*)&gsm[r0 + r][cc] = make_float2(f0, f1);
        }
        __syncthreads();

        {
            const float* pxi = (const float*)&xi;
            const float* pxf = (const float*)&xf;
            const float* pxg = (const float*)&xgv;
            const float* pxo = (const float*)&xo;

            float h4[4];
#pragma unroll
            for (int q = 0; q < 4; q++) {
                int hh = eh + q;
                float gi = gsm[eb][hh]      + pxi[q];
                float gf = gsm[eb][32 + hh] + pxf[q];
                float gg = gsm[eb][64 + hh] + pxg[q];
                float go = gsm[eb][96 + hh] + pxo[q];
                gi = sigmoidf_(gi);
                gf = sigmoidf_(gf);
                gg = tanhf(gg);
                go = sigmoidf_(go);
                float c = fmaf(gf, csm[eb][hh], gi * gg);
                csm[eb][hh] = c;
                h4[q] = go * tanhf(c);
            }
            float4 hv = make_float4(h4[0], h4[1], h4[2], h4[3]);
            *(float4*)&hn[(b0 + eb) * HDIM + h0 + eh] = hv;
            *(float4*)&g_hout[((size_t)(b0 + eb) * TDIM + t) * HDIM + h0 + eh] = hv;
        }

        if (t < TDIM - 1) gb_arrive(nb);
    }
}

// ---------------- Launch orchestration -------------------------------------
extern "C" void kernel_launch(void* const* d_in, const int* in_sizes, int n_in,
                              void* d_out, int out_size)
{
    (void)in_sizes; (void)n_in; (void)out_size;
    const float* x    = (const float*)d_in[0];
    const float* Wih0 = (const float*)d_in[1];
    const float* Whh0 = (const float*)d_in[2];
    const float* bih0 = (const float*)d_in[3];
    const float* bhh0 = (const float*)d_in[4];
    const float* Wih1 = (const float*)d_in[5];
    const float* Whh1 = (const float*)d_in[6];
    const float* bih1 = (const float*)d_in[7];
    const float* bhh1 = (const float*)d_in[8];
    const float* Wlin = (const float*)d_in[9];
    const float* blin = (const float*)d_in[10];
    float* out = (float*)d_out;

    void *pxg = nullptr, *phout = nullptr;
    void *pAhi = nullptr, *pAlo = nullptr, *pWhi = nullptr, *pWlo = nullptr;
    cudaGetSymbolAddress(&pxg, g_xg);
    cudaGetSymbolAddress(&phout, g_hout);
    cudaGetSymbolAddress(&pAhi, g_Ahi);
    cudaGetSymbolAddress(&pAlo, g_Alo);
    cudaGetSymbolAddress(&pWhi, g_Whi);
    cudaGetSymbolAddress(&pWlo, g_Wlo);
    float* xg = (float*)pxg;
    float* hout = (float*)phout;
    __nv_bfloat16* Ahi = (__nv_bfloat16*)pAhi;
    __nv_bfloat16* Alo = (__nv_bfloat16*)pAlo;
    __nv_bfloat16* Whi = (__nv_bfloat16*)pWhi;
    __nv_bfloat16* Wlo = (__nv_bfloat16*)pWlo;

    static int s_attr_done = 0;
    if (!s_attr_done) {
        cudaFuncSetAttribute(gemm_mma, cudaFuncAttributeMaxDynamicSharedMemorySize, GM_SMEM);
        s_attr_done = 1;
    }

    // ---- Layer 0 ----
    split_bf16<<<4096, 256>>>(x, Ahi, Alo, (size_t)MROWS * IDIM / 2);
    split_bf16<<<2048, 256>>>(Wih0, Whi, Wlo, (size_t)G4 * IDIM / 2);
    gemm_mma<<<dim3(G4 / 128, MROWS / 128), 256, GM_SMEM>>>(
        Ahi, Alo, Whi, Wlo, bih0, bhh0, xg, IDIM, G4, 1);
    lstm_scan<<<128, 256>>>(Whh0);

    // ---- Layer 1 ----
    split_bf16<<<4096, 256>>>(hout, Ahi, Alo, (size_t)MROWS * HDIM / 2);
    split_bf16<<<2048, 256>>>(Wih1, Whi, Wlo, (size_t)G4 * HDIM / 2);
    gemm_mma<<<dim3(G4 / 128, MROWS / 128), 256, GM_SMEM>>>(
        Ahi, Alo, Whi, Wlo, bih1, bhh1, xg, HDIM, G4, 1);
    lstm_scan<<<128, 256>>>(Whh1);

    // ---- Output linear ----
    split_bf16<<<4096, 256>>>(hout, Ahi, Alo, (size_t)MROWS * HDIM / 2);
    split_bf16<<<1024, 256>>>(Wlin, Whi, Wlo, (size_t)ODIM * HDIM / 2);
    gemm_mma<<<dim3(ODIM / 128, MROWS / 128), 256, GM_SMEM>>>(
        Ahi, Alo, Whi, Wlo, blin, nullptr, out, HDIM, ODIM, 0);
}